// round 16
// baseline (speedup 1.0000x reference)
#include <cuda_runtime.h>
#include <cuda_bf16.h>
#include <mma.h>
#include <cstdint>

using namespace nvcuda;

#define NN 50000
#define EE 640000
#define HCC 128
#define NHH 4
#define NLAY 4
#define NBATCH 64
#define NCLS 88

// ---------------- scratch (static device globals; no allocation) ----------------
__device__ float g_h[NN * HCC];
__device__ float g_hp[NN * HCC];
__device__ float g_asrc[NN * NHH];
__device__ float g_adst[NN * NHH];
__device__ int   g_deg[NN];
__device__ int   g_off[NN + 1];
__device__ int   g_cur[NN];
__device__ int   g_bsum[64];
__device__ int   g_csr_src[EE];
__device__ float g_tcsr[EE];
__device__ uchar2 g_ij[EE];
__device__ float g_sums[NBATCH * HCC];
__device__ float g_cnt[NBATCH];

// piecewise-linear a_edge tables
__device__ int   d_np, d_nn2;
__device__ float d_thrp[HCC], d_thrn[HCC];
__device__ float4 d_PA[(HCC + 1) * NLAY];
__device__ float4 d_PB[(HCC + 1) * NLAY];
__device__ float4 d_SA[(HCC + 1) * NLAY];
__device__ float4 d_SB[(HCC + 1) * NLAY];
__device__ float4 d_CB[NLAY];

// ---------------- zero ----------------
__global__ void k_zero() {
    int i = blockIdx.x * blockDim.x + threadIdx.x;
    if (i < NN) g_deg[i] = 0;
    if (i < NBATCH * HCC) g_sums[i] = 0.f;
    if (i < NBATCH) g_cnt[i] = 0.f;
}

// ---------------- CSR build ----------------
__global__ void k_hist(const int* __restrict__ dst) {
    int i = blockIdx.x * blockDim.x + threadIdx.x;
    if (i < EE) atomicAdd(&g_deg[dst[i]], 1);
}
__global__ void k_scan1() {
    __shared__ int ws[32];
    int t = threadIdx.x;
    int gi = blockIdx.x * 1024 + t;
    int v = (gi < NN) ? g_deg[gi] : 0;
    int lane = t & 31, wid = t >> 5;
    int x = v;
    #pragma unroll
    for (int o = 1; o < 32; o <<= 1) {
        int y = __shfl_up_sync(~0u, x, o);
        if (lane >= o) x += y;
    }
    if (lane == 31) ws[wid] = x;
    __syncthreads();
    if (wid == 0) {
        int y = ws[lane];
        #pragma unroll
        for (int o = 1; o < 32; o <<= 1) {
            int z = __shfl_up_sync(~0u, y, o);
            if (lane >= o) y += z;
        }
        ws[lane] = y;
    }
    __syncthreads();
    int excl = x - v + (wid ? ws[wid - 1] : 0);
    if (gi < NN) g_off[gi] = excl;
    if (t == 1023) g_bsum[blockIdx.x] = excl + v;
}
__global__ void k_scan2() {
    __shared__ int sm2[64];
    int t = threadIdx.x;
    int v = (t < 49) ? g_bsum[t] : 0;
    sm2[t] = v;
    __syncthreads();
    #pragma unroll
    for (int o = 1; o < 64; o <<= 1) {
        int x = (t >= o) ? sm2[t - o] : 0;
        __syncthreads();
        sm2[t] += x;
        __syncthreads();
    }
    if (t < 49) g_bsum[t] = sm2[t] - v;
}
__global__ void k_scan3() {
    int i = blockIdx.x * blockDim.x + threadIdx.x;
    if (i < NN) {
        int o = g_off[i] + g_bsum[i >> 10];
        g_off[i] = o;
        g_cur[i] = o;
    }
    if (i == 0) g_off[NN] = EE;
}
__global__ void k_scatter(const int* __restrict__ src, const int* __restrict__ dst,
                          const float* __restrict__ eattr) {
    int i = blockIdx.x * blockDim.x + threadIdx.x;
    if (i >= EE) return;
    int p = atomicAdd(&g_cur[dst[i]], 1);
    float tv = eattr[i];
    g_csr_src[p] = src[i];
    g_tcsr[p] = tv;
    int np = d_np, nn = d_nn2;
    int lo = 0, hi = np;
    while (lo < hi) { int m = (lo + hi) >> 1; if (d_thrp[m] < tv) lo = m + 1; else hi = m; }
    int ii = lo;
    lo = 0; hi = nn;
    while (lo < hi) { int m = (lo + hi) >> 1; if (d_thrn[m] <= tv) lo = m + 1; else hi = m; }
    g_ij[p] = make_uchar2((unsigned char)ii, (unsigned char)lo);
}

// ---------------- node encoder ----------------
__global__ void k_node_enc(const float* __restrict__ x, const float* __restrict__ W,
                           const float* __restrict__ b, const float* __restrict__ g,
                           const float* __restrict__ be) {
    int t = threadIdx.x;
    int n = blockIdx.x * 8 + (t >> 5);
    if (n >= NN) return;
    int lane = t & 31;
    float4 xv = ((const float4*)x)[n];
    const float4* Wr = (const float4*)W;
    float4 w0 = Wr[lane], w1 = Wr[32 + lane], w2 = Wr[64 + lane], w3 = Wr[96 + lane];
    float4 bv = ((const float4*)b)[lane];
    float4 y;
    y.x = bv.x + xv.x * w0.x + xv.y * w1.x + xv.z * w2.x + xv.w * w3.x;
    y.y = bv.y + xv.x * w0.y + xv.y * w1.y + xv.z * w2.y + xv.w * w3.y;
    y.z = bv.z + xv.x * w0.z + xv.y * w1.z + xv.z * w2.z + xv.w * w3.z;
    y.w = bv.w + xv.x * w0.w + xv.y * w1.w + xv.z * w2.w + xv.w * w3.w;
    float s1 = y.x + y.y + y.z + y.w;
    float s2 = y.x * y.x + y.y * y.y + y.z * y.z + y.w * y.w;
    #pragma unroll
    for (int o = 16; o; o >>= 1) {
        s1 += __shfl_xor_sync(~0u, s1, o);
        s2 += __shfl_xor_sync(~0u, s2, o);
    }
    float mean = s1 * (1.f / HCC);
    float var = s2 * (1.f / HCC) - mean * mean;
    float rstd = rsqrtf(var + 1e-5f);
    float4 gv = ((const float4*)g)[lane];
    float4 bev = ((const float4*)be)[lane];
    float4 r;
    r.x = fmaxf((y.x - mean) * rstd * gv.x + bev.x, 0.f);
    r.y = fmaxf((y.y - mean) * rstd * gv.y + bev.y, 0.f);
    r.z = fmaxf((y.z - mean) * rstd * gv.z + bev.z, 0.f);
    r.w = fmaxf((y.w - mean) * rstd * gv.w + bev.w, 0.f);
    ((float4*)g_h)[n * 32 + lane] = r;
}

// ---------------- piecewise a_edge tables (1 block, 128 threads) ----------------
__global__ void k_prep(const float* __restrict__ We, const float* __restrict__ atte,
                       const float* __restrict__ Wee, const float* __restrict__ bee) {
    __shared__ float stau[HCC], sw_[HCC], sb_[HCC];
    __shared__ int sflag[HCC];
    __shared__ float swm[NLAY * NHH][HCC];
    __shared__ float sbm[NLAY * NHH][HCC];
    __shared__ int srtp[HCC], srtn[HCC];
    __shared__ int s_np, s_nn;
    int k = threadIdx.x;
    if (k == 0) { s_np = 0; s_nn = 0; }
    float w = Wee[k], b = bee[k];
    #pragma unroll
    for (int l = 0; l < NLAY; l++) {
        #pragma unroll
        for (int h = 0; h < NHH; h++) {
            float m = 0.f;
            #pragma unroll 8
            for (int c = 0; c < 32; c++)
                m += We[l * HCC * HCC + k * HCC + h * 32 + c] * atte[l * HCC + h * 32 + c];
            swm[l * NHH + h][k] = w * m;
            sbm[l * NHH + h][k] = b * m;
        }
    }
    sw_[k] = w; sb_[k] = b;
    int flag = (w > 0.f) ? 0 : ((w < 0.f) ? 1 : 2);
    sflag[k] = flag;
    stau[k] = (flag < 2) ? (-b / w) : 0.f;
    __syncthreads();
    float tk = stau[k];
    int rank = 0, cnt = 0;
    if (flag < 2) {
        for (int j = 0; j < HCC; j++)
            if (sflag[j] == flag) {
                cnt++;
                if (stau[j] < tk || (stau[j] == tk && j < k)) rank++;
            }
    }
    if (flag == 0 && rank == 0) s_np = cnt;
    if (flag == 1 && rank == 0) s_nn = cnt;
    if (flag == 0) { srtp[rank] = k; d_thrp[rank] = tk; }
    if (flag == 1) { srtn[rank] = k; d_thrn[rank] = tk; }
    __syncthreads();
    int np = s_np, nn = s_nn;
    float* PAf = (float*)d_PA; float* PBf = (float*)d_PB;
    float* SAf = (float*)d_SA; float* SBf = (float*)d_SB;
    float* CBf = (float*)d_CB;
    if (k < 16) {
        int c = k, l = k >> 2, h = k & 3;
        float ra = 0.f, rb = 0.f;
        PAf[(0 * NLAY + l) * 4 + h] = 0.f;
        PBf[(0 * NLAY + l) * 4 + h] = 0.f;
        for (int i = 0; i < np; i++) {
            int kk = srtp[i];
            ra += swm[c][kk]; rb += sbm[c][kk];
            PAf[((i + 1) * NLAY + l) * 4 + h] = ra;
            PBf[((i + 1) * NLAY + l) * 4 + h] = rb;
        }
    } else if (k < 32) {
        int c = k - 16, l = c >> 2, h = c & 3;
        float ra = 0.f, rb = 0.f;
        SAf[(nn * NLAY + l) * 4 + h] = 0.f;
        SBf[(nn * NLAY + l) * 4 + h] = 0.f;
        for (int i = nn - 1; i >= 0; i--) {
            int kk = srtn[i];
            ra += swm[c][kk]; rb += sbm[c][kk];
            SAf[(i * NLAY + l) * 4 + h] = ra;
            SBf[(i * NLAY + l) * 4 + h] = rb;
        }
    } else if (k < 48) {
        int c = k - 32;
        float r = 0.f;
        for (int j = 0; j < HCC; j++)
            if (sflag[j] == 2 && sb_[j] > 0.f) r += sbm[c][j];
        CBf[c] = r;
    }
    if (k == 0) { d_np = np; d_nn2 = nn; }
}

// ---- wmma GEMM: hp = h @ W via split-bf16 (AhiBhi + AhiBlo + AloBhi) ----
// smem: Ahi [128][128] bf16 | Alo | Bhi | Blo  (32KB each, 128KB total)
// Ahi+Alo region doubles as fp32 staging (64KB) for the OOB tail tile.
#define SM_AHI 0
#define SM_ALO 32768
#define SM_BHI 65536
#define SM_BLO 98304
#define SMEM_T 131072
#define NT ((NN + 127) / 128)

__global__ __launch_bounds__(256, 1) void k_gemm(const float* __restrict__ W) {
    extern __shared__ char smem[];
    __nv_bfloat16* Ah = (__nv_bfloat16*)(smem + SM_AHI);
    __nv_bfloat16* Al = (__nv_bfloat16*)(smem + SM_ALO);
    __nv_bfloat16* Bh = (__nv_bfloat16*)(smem + SM_BHI);
    __nv_bfloat16* Bl = (__nv_bfloat16*)(smem + SM_BLO);
    float* Cst = (float*)(smem + SM_AHI);   // tail staging
    int tid = threadIdx.x;
    int wid = tid >> 5;
    int m0 = wid * 16;

    // convert W [K][N] (N contiguous) -> Bh/Bl row-major, same layout
    const float4* W4 = (const float4*)W;
    for (int i = tid; i < 4096; i += 256) {
        float4 v = W4[i];
        int off = i * 4;
        __nv_bfloat16 h;
        h = __float2bfloat16_rn(v.x); Bh[off]     = h; Bl[off]     = __float2bfloat16_rn(v.x - __bfloat162float(h));
        h = __float2bfloat16_rn(v.y); Bh[off + 1] = h; Bl[off + 1] = __float2bfloat16_rn(v.y - __bfloat162float(h));
        h = __float2bfloat16_rn(v.z); Bh[off + 2] = h; Bl[off + 2] = __float2bfloat16_rn(v.z - __bfloat162float(h));
        h = __float2bfloat16_rn(v.w); Bh[off + 3] = h; Bl[off + 3] = __float2bfloat16_rn(v.w - __bfloat162float(h));
    }

    const float4* gh4 = (const float4*)g_h;
    for (int tile = blockIdx.x; tile < NT; tile += gridDim.x) {
        int base = tile * 128;
        __syncthreads();   // previous iteration's A reads / staging done
        for (int it = 0; it < 16; it++) {
            int f = tid + it * 256;          // float4 index within tile
            int row = f >> 5, q = f & 31;
            int gr = base + row;
            float4 v = (gr < NN) ? gh4[gr * 32 + q] : make_float4(0.f, 0.f, 0.f, 0.f);
            int off = row * 128 + q * 4;
            __nv_bfloat16 h;
            h = __float2bfloat16_rn(v.x); Ah[off]     = h; Al[off]     = __float2bfloat16_rn(v.x - __bfloat162float(h));
            h = __float2bfloat16_rn(v.y); Ah[off + 1] = h; Al[off + 1] = __float2bfloat16_rn(v.y - __bfloat162float(h));
            h = __float2bfloat16_rn(v.z); Ah[off + 2] = h; Al[off + 2] = __float2bfloat16_rn(v.z - __bfloat162float(h));
            h = __float2bfloat16_rn(v.w); Ah[off + 3] = h; Al[off + 3] = __float2bfloat16_rn(v.w - __bfloat162float(h));
        }
        __syncthreads();

        wmma::fragment<wmma::accumulator, 16, 16, 16, float> c[8];
        #pragma unroll
        for (int j = 0; j < 8; j++) wmma::fill_fragment(c[j], 0.f);
        #pragma unroll
        for (int kk = 0; kk < 8; kk++) {
            wmma::fragment<wmma::matrix_a, 16, 16, 16, __nv_bfloat16, wmma::row_major> ah, al;
            wmma::load_matrix_sync(ah, Ah + m0 * 128 + kk * 16, 128);
            wmma::load_matrix_sync(al, Al + m0 * 128 + kk * 16, 128);
            #pragma unroll
            for (int j = 0; j < 8; j++) {
                wmma::fragment<wmma::matrix_b, 16, 16, 16, __nv_bfloat16, wmma::row_major> bh, bl;
                wmma::load_matrix_sync(bh, Bh + kk * 16 * 128 + j * 16, 128);
                wmma::load_matrix_sync(bl, Bl + kk * 16 * 128 + j * 16, 128);
                wmma::mma_sync(c[j], ah, bh, c[j]);
                wmma::mma_sync(c[j], ah, bl, c[j]);
                wmma::mma_sync(c[j], al, bh, c[j]);
            }
        }
        if (base + 128 <= NN) {
            #pragma unroll
            for (int j = 0; j < 8; j++)
                wmma::store_matrix_sync(g_hp + (size_t)(base + m0) * 128 + j * 16, c[j], 128,
                                        wmma::mem_row_major);
        } else {
            __syncthreads();   // A-frag reads complete before staging overwrites Ah/Al
            #pragma unroll
            for (int j = 0; j < 8; j++)
                wmma::store_matrix_sync(Cst + m0 * 128 + j * 16, c[j], 128, wmma::mem_row_major);
            __syncthreads();
            for (int idx = tid; idx < 4096; idx += 256) {
                int row = idx >> 5, q = idx & 31;
                if (base + row < NN)
                    ((float4*)g_hp)[(size_t)(base + row) * 32 + q] = ((const float4*)Cst)[row * 32 + q];
            }
        }
    }
}

// ---------------- a_src / a_dst from g_hp (R6-proven) ----------------
__global__ void k_attn(const float* __restrict__ atts, const float* __restrict__ attd) {
    __shared__ float ss[HCC], sd[HCC];
    int t = threadIdx.x;
    if (t < HCC) { ss[t] = atts[t]; sd[t] = attd[t]; }
    __syncthreads();
    int n = blockIdx.x * 8 + (t >> 5);
    if (n >= NN) return;
    int lane = t & 31;
    float4 p = ((const float4*)g_hp)[n * 32 + lane];
    int c = lane * 4;
    float vs = p.x * ss[c] + p.y * ss[c + 1] + p.z * ss[c + 2] + p.w * ss[c + 3];
    float vd = p.x * sd[c] + p.y * sd[c + 1] + p.z * sd[c + 2] + p.w * sd[c + 3];
    #pragma unroll
    for (int o = 4; o; o >>= 1) {
        vs += __shfl_xor_sync(~0u, vs, o);
        vd += __shfl_xor_sync(~0u, vd, o);
    }
    if ((lane & 7) == 0) {
        g_asrc[n * NHH + (lane >> 3)] = vs;
        g_adst[n * NHH + (lane >> 3)] = vd;
    }
}

// ---- single-pass softmax-aggregate (R6-proven serial form) ----
__global__ void k_agg(const float* __restrict__ bias, const float* __restrict__ gam,
                      const float* __restrict__ bet, int layer) {
    int t = threadIdx.x;
    int n = blockIdx.x * 8 + (t >> 5);
    if (n >= NN) return;
    int lane = t & 31;
    int hh = lane >> 3;
    int o0 = g_off[n];
    int deg = g_off[n + 1] - o0;
    float adh = g_adst[n * NHH + hh];
    const float* PAf = (const float*)d_PA + layer * 4 + hh;   // stride 16 per index
    const float* PBf = (const float*)d_PB + layer * 4 + hh;
    const float* SAf = (const float*)d_SA + layer * 4 + hh;
    const float* SBf = (const float*)d_SB + layer * 4 + hh;
    float cb = ((const float*)d_CB)[layer * 4 + hh];
    const float4* hp4 = (const float4*)g_hp;

    float4 acc = make_float4(0.f, 0.f, 0.f, 0.f);
    float den = 0.f;
    int j = 0;
    for (; j + 1 < deg; j += 2) {
        int p0 = o0 + j, p1 = o0 + j + 1;
        int s0 = g_csr_src[p0], s1 = g_csr_src[p1];
        float tv0 = g_tcsr[p0], tv1 = g_tcsr[p1];
        uchar2 ij0 = g_ij[p0], ij1 = g_ij[p1];
        float as0 = g_asrc[s0 * NHH + hh], as1 = g_asrc[s1 * NHH + hh];
        float4 hp0 = hp4[s0 * 32 + lane];
        float4 hp1 = hp4[s1 * 32 + lane];
        float ae0 = tv0 * (PAf[ij0.x * 16] + SAf[ij0.y * 16]) + PBf[ij0.x * 16] + SBf[ij0.y * 16] + cb;
        float ae1 = tv1 * (PAf[ij1.x * 16] + SAf[ij1.y * 16]) + PBf[ij1.x * 16] + SBf[ij1.y * 16] + cb;
        float a0 = as0 + adh + ae0; a0 = a0 >= 0.f ? a0 : 0.2f * a0;
        float a1 = as1 + adh + ae1; a1 = a1 >= 0.f ? a1 : 0.2f * a1;
        float w0 = __expf(a0);
        float w1 = __expf(a1);
        den += w0 + w1;
        acc.x += w0 * hp0.x + w1 * hp1.x;
        acc.y += w0 * hp0.y + w1 * hp1.y;
        acc.z += w0 * hp0.z + w1 * hp1.z;
        acc.w += w0 * hp0.w + w1 * hp1.w;
    }
    if (j < deg) {
        int p = o0 + j;
        int s = g_csr_src[p];
        float tv = g_tcsr[p];
        uchar2 ij = g_ij[p];
        float ae = tv * (PAf[ij.x * 16] + SAf[ij.y * 16]) + PBf[ij.x * 16] + SBf[ij.y * 16] + cb;
        float a = g_asrc[s * NHH + hh] + adh + ae;
        a = a >= 0.f ? a : 0.2f * a;
        float w = __expf(a);
        float4 hp = hp4[s * 32 + lane];
        den += w;
        acc.x += w * hp.x; acc.y += w * hp.y; acc.z += w * hp.z; acc.w += w * hp.w;
    }
    float rden = den > 0.f ? 1.f / den : 0.f;

    float4 bv = ((const float4*)bias)[lane];
    float4 v = make_float4(acc.x * rden + bv.x, acc.y * rden + bv.y,
                           acc.z * rden + bv.z, acc.w * rden + bv.w);
    float s1 = v.x + v.y + v.z + v.w;
    float s2 = v.x * v.x + v.y * v.y + v.z * v.z + v.w * v.w;
    #pragma unroll
    for (int o = 16; o; o >>= 1) {
        s1 += __shfl_xor_sync(~0u, s1, o);
        s2 += __shfl_xor_sync(~0u, s2, o);
    }
    float mean = s1 * (1.f / HCC);
    float var = s2 * (1.f / HCC) - mean * mean;
    float rstd = rsqrtf(var + 1e-5f);
    float4 gv = ((const float4*)gam)[lane];
    float4 bev = ((const float4*)bet)[lane];
    float4 hold = ((const float4*)g_h)[n * 32 + lane];
    float4 r;
    r.x = hold.x + fmaxf((v.x - mean) * rstd * gv.x + bev.x, 0.f);
    r.y = hold.y + fmaxf((v.y - mean) * rstd * gv.y + bev.y, 0.f);
    r.z = hold.z + fmaxf((v.z - mean) * rstd * gv.z + bev.z, 0.f);
    r.w = hold.w + fmaxf((v.w - mean) * rstd * gv.w + bev.w, 0.f);
    ((float4*)g_h)[n * 32 + lane] = r;
}

// ---------------- pooling (count folded in) + classifier ----------------
__global__ void k_pool(const int* __restrict__ batch) {
    int n0 = blockIdx.x * 256;
    int n1 = n0 + 256; if (n1 > NN) n1 = NN;
    int c = threadIdx.x;
    float run = 0.f, runc = 0.f;
    int curb = batch[n0];
    for (int n = n0; n < n1; n++) {
        int b = batch[n];
        if (b != curb) {
            atomicAdd(&g_sums[curb * HCC + c], run);
            if (c == 0) atomicAdd(&g_cnt[curb], runc);
            run = 0.f; runc = 0.f; curb = b;
        }
        run += g_h[n * HCC + c];
        runc += 1.f;
    }
    atomicAdd(&g_sums[curb * HCC + c], run);
    if (c == 0) atomicAdd(&g_cnt[curb], runc);
}
__global__ void k_cls(const float* __restrict__ W1, const float* __restrict__ b1,
                      const float* __restrict__ W2, const float* __restrict__ b2,
                      float* __restrict__ out) {
    __shared__ float sp[HCC];
    __shared__ float sz[64];
    int b = blockIdx.x;
    int c = threadIdx.x;
    float cnt = fmaxf(g_cnt[b], 1.f);
    sp[c] = g_sums[b * HCC + c] / cnt;
    __syncthreads();
    if (c < 64) {
        float a = b1[c];
        #pragma unroll 4
        for (int k = 0; k < HCC; k++) a += sp[k] * W1[k * 64 + c];
        sz[c] = fmaxf(a, 0.f);
    }
    __syncthreads();
    if (c < NCLS) {
        float a = b2[c];
        #pragma unroll 4
        for (int k = 0; k < 64; k++) a += sz[k] * W2[k * NCLS + c];
        out[b * NCLS + c] = a;
    }
}

// ---------------- launch ----------------
extern "C" void kernel_launch(void* const* d_in, const int* in_sizes, int n_in,
                              void* d_out, int out_size) {
    (void)in_sizes; (void)n_in; (void)out_size;
    const float* x     = (const float*)d_in[0];
    const float* eattr = (const float*)d_in[1];
    const int*   eidx  = (const int*)d_in[2];
    const int*   batch = (const int*)d_in[3];
    const float* W_ne  = (const float*)d_in[4];
    const float* b_ne  = (const float*)d_in[5];
    const float* g_ne  = (const float*)d_in[6];
    const float* be_ne = (const float*)d_in[7];
    const float* W_ee  = (const float*)d_in[8];
    const float* b_ee  = (const float*)d_in[9];
    const float* Wl    = (const float*)d_in[10];
    const float* att_s = (const float*)d_in[11];
    const float* att_d = (const float*)d_in[12];
    const float* We    = (const float*)d_in[13];
    const float* att_e = (const float*)d_in[14];
    const float* b_l   = (const float*)d_in[15];
    const float* g_l   = (const float*)d_in[16];
    const float* be_l  = (const float*)d_in[17];
    const float* W1    = (const float*)d_in[18];
    const float* b1    = (const float*)d_in[19];
    const float* W2    = (const float*)d_in[20];
    const float* b2    = (const float*)d_in[21];
    float* out = (float*)d_out;

    const int* src = eidx;
    const int* dst = eidx + EE;

    cudaFuncSetAttribute(k_gemm, cudaFuncAttributeMaxDynamicSharedMemorySize, SMEM_T);

    // tables first (k_scatter needs thresholds)
    k_prep<<<1, HCC>>>(We, att_e, W_ee, b_ee);

    // CSR build + zero
    k_zero<<<(NN + 255) / 256, 256>>>();
    k_hist<<<(EE + 255) / 256, 256>>>(dst);
    k_scan1<<<49, 1024>>>();
    k_scan2<<<1, 64>>>();
    k_scan3<<<(NN + 255) / 256, 256>>>();
    k_scatter<<<(EE + 255) / 256, 256>>>(src, dst, eattr);

    // node encoder
    k_node_enc<<<(NN + 7) / 8, 256>>>(x, W_ne, b_ne, g_ne, be_ne);

    for (int l = 0; l < NLAY; l++) {
        k_gemm<<<148, 256, SMEM_T>>>(Wl + l * HCC * HCC);
        k_attn<<<(NN + 7) / 8, 256>>>(att_s + l * HCC, att_d + l * HCC);
        k_agg<<<(NN + 7) / 8, 256>>>(b_l + l * HCC, g_l + l * HCC, be_l + l * HCC, l);
    }

    // pooling + classifier
    k_pool<<<(NN + 255) / 256, HCC>>>(batch);
    k_cls<<<NBATCH, HCC>>>(W1, b1, W2, b2, out);
}

// round 17
// speedup vs baseline: 1.0282x; 1.0282x over previous
#include <cuda_runtime.h>
#include <cuda_bf16.h>
#include <mma.h>
#include <cstdint>

using namespace nvcuda;

#define NN 50000
#define EE 640000
#define HCC 128
#define NHH 4
#define NLAY 4
#define NBATCH 64
#define NCLS 88
#define NT 391
#define NPAD (NT * 128)   // 50048 rows, pad rows zeroed

// ---------------- scratch (static device globals; no allocation) ----------------
__device__ float g_h[NN * HCC];
__device__ __nv_bfloat16 g_hbh[NPAD * HCC];
__device__ __nv_bfloat16 g_hbl[NPAD * HCC];
__device__ float g_hp[NPAD * HCC];
__device__ __nv_bfloat16 g_Wbh[NLAY * HCC * HCC];
__device__ __nv_bfloat16 g_Wbl[NLAY * HCC * HCC];
__device__ float g_asrc[NN * NHH];
__device__ float g_adst[NN * NHH];
__device__ int   g_deg[NN];
__device__ int   g_off[NN + 1];
__device__ int   g_cur[NN];
__device__ int   g_bsum[64];
__device__ int   g_csr_src[EE];
__device__ float g_tcsr[EE];
__device__ uchar2 g_ij[EE];
__device__ float g_sums[NBATCH * HCC];
__device__ float g_cnt[NBATCH];

// piecewise-linear a_edge tables
__device__ int   d_np, d_nn2;
__device__ float d_thrp[HCC], d_thrn[HCC];
__device__ float4 d_PA[(HCC + 1) * NLAY];
__device__ float4 d_PB[(HCC + 1) * NLAY];
__device__ float4 d_SA[(HCC + 1) * NLAY];
__device__ float4 d_SB[(HCC + 1) * NLAY];
__device__ float4 d_CB[NLAY];

__device__ __forceinline__ void split_store(float v, __nv_bfloat16* ph, __nv_bfloat16* pl) {
    __nv_bfloat16 hi = __float2bfloat16_rn(v);
    *ph = hi;
    *pl = __float2bfloat16_rn(v - __bfloat162float(hi));
}

// ---------------- zero ----------------
__global__ void k_zero() {
    int i = blockIdx.x * blockDim.x + threadIdx.x;
    if (i < NN) g_deg[i] = 0;
    if (i < NBATCH * HCC) g_sums[i] = 0.f;
    if (i < NBATCH) g_cnt[i] = 0.f;
    if (i < (NPAD - NN) * HCC) {           // zero pad rows of split-h
        g_hbh[NN * HCC + i] = __float2bfloat16_rn(0.f);
        g_hbl[NN * HCC + i] = __float2bfloat16_rn(0.f);
    }
}

// ---------------- W -> bf16 hi/lo (all layers) ----------------
__global__ void k_wconv(const float* __restrict__ Wl) {
    int i = blockIdx.x * blockDim.x + threadIdx.x;
    if (i < NLAY * HCC * HCC) {
        float v = Wl[i];
        split_store(v, &g_Wbh[i], &g_Wbl[i]);
    }
}

// ---------------- CSR build ----------------
__global__ void k_hist(const int* __restrict__ dst) {
    int i = blockIdx.x * blockDim.x + threadIdx.x;
    if (i < EE) atomicAdd(&g_deg[dst[i]], 1);
}
__global__ void k_scan1() {
    __shared__ int ws[32];
    int t = threadIdx.x;
    int gi = blockIdx.x * 1024 + t;
    int v = (gi < NN) ? g_deg[gi] : 0;
    int lane = t & 31, wid = t >> 5;
    int x = v;
    #pragma unroll
    for (int o = 1; o < 32; o <<= 1) {
        int y = __shfl_up_sync(~0u, x, o);
        if (lane >= o) x += y;
    }
    if (lane == 31) ws[wid] = x;
    __syncthreads();
    if (wid == 0) {
        int y = ws[lane];
        #pragma unroll
        for (int o = 1; o < 32; o <<= 1) {
            int z = __shfl_up_sync(~0u, y, o);
            if (lane >= o) y += z;
        }
        ws[lane] = y;
    }
    __syncthreads();
    int excl = x - v + (wid ? ws[wid - 1] : 0);
    if (gi < NN) g_off[gi] = excl;
    if (t == 1023) g_bsum[blockIdx.x] = excl + v;
}
__global__ void k_scan2() {
    __shared__ int sm2[64];
    int t = threadIdx.x;
    int v = (t < 49) ? g_bsum[t] : 0;
    sm2[t] = v;
    __syncthreads();
    #pragma unroll
    for (int o = 1; o < 64; o <<= 1) {
        int x = (t >= o) ? sm2[t - o] : 0;
        __syncthreads();
        sm2[t] += x;
        __syncthreads();
    }
    if (t < 49) g_bsum[t] = sm2[t] - v;
}
__global__ void k_scan3() {
    int i = blockIdx.x * blockDim.x + threadIdx.x;
    if (i < NN) {
        int o = g_off[i] + g_bsum[i >> 10];
        g_off[i] = o;
        g_cur[i] = o;
    }
    if (i == 0) g_off[NN] = EE;
}
__global__ void k_scatter(const int* __restrict__ src, const int* __restrict__ dst,
                          const float* __restrict__ eattr) {
    int i = blockIdx.x * blockDim.x + threadIdx.x;
    if (i >= EE) return;
    int p = atomicAdd(&g_cur[dst[i]], 1);
    float tv = eattr[i];
    g_csr_src[p] = src[i];
    g_tcsr[p] = tv;
    int np = d_np, nn = d_nn2;
    int lo = 0, hi = np;
    while (lo < hi) { int m = (lo + hi) >> 1; if (d_thrp[m] < tv) lo = m + 1; else hi = m; }
    int ii = lo;
    lo = 0; hi = nn;
    while (lo < hi) { int m = (lo + hi) >> 1; if (d_thrn[m] <= tv) lo = m + 1; else hi = m; }
    g_ij[p] = make_uchar2((unsigned char)ii, (unsigned char)lo);
}

// ---------------- node encoder (also writes split-bf16 h) ----------------
__global__ void k_node_enc(const float* __restrict__ x, const float* __restrict__ W,
                           const float* __restrict__ b, const float* __restrict__ g,
                           const float* __restrict__ be) {
    int t = threadIdx.x;
    int n = blockIdx.x * 8 + (t >> 5);
    if (n >= NN) return;
    int lane = t & 31;
    float4 xv = ((const float4*)x)[n];
    const float4* Wr = (const float4*)W;
    float4 w0 = Wr[lane], w1 = Wr[32 + lane], w2 = Wr[64 + lane], w3 = Wr[96 + lane];
    float4 bv = ((const float4*)b)[lane];
    float4 y;
    y.x = bv.x + xv.x * w0.x + xv.y * w1.x + xv.z * w2.x + xv.w * w3.x;
    y.y = bv.y + xv.x * w0.y + xv.y * w1.y + xv.z * w2.y + xv.w * w3.y;
    y.z = bv.z + xv.x * w0.z + xv.y * w1.z + xv.z * w2.z + xv.w * w3.z;
    y.w = bv.w + xv.x * w0.w + xv.y * w1.w + xv.z * w2.w + xv.w * w3.w;
    float s1 = y.x + y.y + y.z + y.w;
    float s2 = y.x * y.x + y.y * y.y + y.z * y.z + y.w * y.w;
    #pragma unroll
    for (int o = 16; o; o >>= 1) {
        s1 += __shfl_xor_sync(~0u, s1, o);
        s2 += __shfl_xor_sync(~0u, s2, o);
    }
    float mean = s1 * (1.f / HCC);
    float var = s2 * (1.f / HCC) - mean * mean;
    float rstd = rsqrtf(var + 1e-5f);
    float4 gv = ((const float4*)g)[lane];
    float4 bev = ((const float4*)be)[lane];
    float4 r;
    r.x = fmaxf((y.x - mean) * rstd * gv.x + bev.x, 0.f);
    r.y = fmaxf((y.y - mean) * rstd * gv.y + bev.y, 0.f);
    r.z = fmaxf((y.z - mean) * rstd * gv.z + bev.z, 0.f);
    r.w = fmaxf((y.w - mean) * rstd * gv.w + bev.w, 0.f);
    ((float4*)g_h)[n * 32 + lane] = r;
    int o4 = n * HCC + lane * 4;
    split_store(r.x, &g_hbh[o4],     &g_hbl[o4]);
    split_store(r.y, &g_hbh[o4 + 1], &g_hbl[o4 + 1]);
    split_store(r.z, &g_hbh[o4 + 2], &g_hbl[o4 + 2]);
    split_store(r.w, &g_hbh[o4 + 3], &g_hbl[o4 + 3]);
}

// ---------------- piecewise a_edge tables (1 block, 128 threads) ----------------
__global__ void k_prep(const float* __restrict__ We, const float* __restrict__ atte,
                       const float* __restrict__ Wee, const float* __restrict__ bee) {
    __shared__ float stau[HCC], sw_[HCC], sb_[HCC];
    __shared__ int sflag[HCC];
    __shared__ float swm[NLAY * NHH][HCC];
    __shared__ float sbm[NLAY * NHH][HCC];
    __shared__ int srtp[HCC], srtn[HCC];
    __shared__ int s_np, s_nn;
    int k = threadIdx.x;
    if (k == 0) { s_np = 0; s_nn = 0; }
    float w = Wee[k], b = bee[k];
    #pragma unroll
    for (int l = 0; l < NLAY; l++) {
        #pragma unroll
        for (int h = 0; h < NHH; h++) {
            float m = 0.f;
            #pragma unroll 8
            for (int c = 0; c < 32; c++)
                m += We[l * HCC * HCC + k * HCC + h * 32 + c] * atte[l * HCC + h * 32 + c];
            swm[l * NHH + h][k] = w * m;
            sbm[l * NHH + h][k] = b * m;
        }
    }
    sw_[k] = w; sb_[k] = b;
    int flag = (w > 0.f) ? 0 : ((w < 0.f) ? 1 : 2);
    sflag[k] = flag;
    stau[k] = (flag < 2) ? (-b / w) : 0.f;
    __syncthreads();
    float tk = stau[k];
    int rank = 0, cnt = 0;
    if (flag < 2) {
        for (int j = 0; j < HCC; j++)
            if (sflag[j] == flag) {
                cnt++;
                if (stau[j] < tk || (stau[j] == tk && j < k)) rank++;
            }
    }
    if (flag == 0 && rank == 0) s_np = cnt;
    if (flag == 1 && rank == 0) s_nn = cnt;
    if (flag == 0) { srtp[rank] = k; d_thrp[rank] = tk; }
    if (flag == 1) { srtn[rank] = k; d_thrn[rank] = tk; }
    __syncthreads();
    int np = s_np, nn = s_nn;
    float* PAf = (float*)d_PA; float* PBf = (float*)d_PB;
    float* SAf = (float*)d_SA; float* SBf = (float*)d_SB;
    float* CBf = (float*)d_CB;
    if (k < 16) {
        int c = k, l = k >> 2, h = k & 3;
        float ra = 0.f, rb = 0.f;
        PAf[(0 * NLAY + l) * 4 + h] = 0.f;
        PBf[(0 * NLAY + l) * 4 + h] = 0.f;
        for (int i = 0; i < np; i++) {
            int kk = srtp[i];
            ra += swm[c][kk]; rb += sbm[c][kk];
            PAf[((i + 1) * NLAY + l) * 4 + h] = ra;
            PBf[((i + 1) * NLAY + l) * 4 + h] = rb;
        }
    } else if (k < 32) {
        int c = k - 16, l = c >> 2, h = c & 3;
        float ra = 0.f, rb = 0.f;
        SAf[(nn * NLAY + l) * 4 + h] = 0.f;
        SBf[(nn * NLAY + l) * 4 + h] = 0.f;
        for (int i = nn - 1; i >= 0; i--) {
            int kk = srtn[i];
            ra += swm[c][kk]; rb += sbm[c][kk];
            SAf[(i * NLAY + l) * 4 + h] = ra;
            SBf[(i * NLAY + l) * 4 + h] = rb;
        }
    } else if (k < 48) {
        int c = k - 32;
        float r = 0.f;
        for (int j = 0; j < HCC; j++)
            if (sflag[j] == 2 && sb_[j] > 0.f) r += sbm[c][j];
        CBf[c] = r;
    }
    if (k == 0) { d_np = np; d_nn2 = nn; }
}

// ---- wmma GEMM, all operands GLOBAL, zero smem, B-frags hoisted to registers ----
// warp w owns n-columns [w*16, w*16+16); per tile: 8 m-subtiles x 8 k-steps x 3 mma.
__global__ __launch_bounds__(256, 2) void k_gemm(int layer) {
    int wid = threadIdx.x >> 5;
    const __nv_bfloat16* Wh = g_Wbh + layer * HCC * HCC + wid * 16;
    const __nv_bfloat16* Wl_ = g_Wbl + layer * HCC * HCC + wid * 16;

    wmma::fragment<wmma::matrix_b, 16, 16, 16, __nv_bfloat16, wmma::row_major> bh[8], bl[8];
    #pragma unroll
    for (int kk = 0; kk < 8; kk++) {
        wmma::load_matrix_sync(bh[kk], Wh + kk * 16 * HCC, HCC);
        wmma::load_matrix_sync(bl[kk], Wl_ + kk * 16 * HCC, HCC);
    }

    for (int tile = blockIdx.x; tile < NT; tile += gridDim.x) {
        int base = tile * 128;
        #pragma unroll 2
        for (int m = 0; m < 8; m++) {
            const __nv_bfloat16* Ah = g_hbh + (size_t)(base + m * 16) * HCC;
            const __nv_bfloat16* Al = g_hbl + (size_t)(base + m * 16) * HCC;
            wmma::fragment<wmma::accumulator, 16, 16, 16, float> c;
            wmma::fill_fragment(c, 0.f);
            #pragma unroll
            for (int kk = 0; kk < 8; kk++) {
                wmma::fragment<wmma::matrix_a, 16, 16, 16, __nv_bfloat16, wmma::row_major> ah, al;
                wmma::load_matrix_sync(ah, Ah + kk * 16, HCC);
                wmma::load_matrix_sync(al, Al + kk * 16, HCC);
                wmma::mma_sync(c, ah, bh[kk], c);
                wmma::mma_sync(c, ah, bl[kk], c);
                wmma::mma_sync(c, al, bh[kk], c);
            }
            wmma::store_matrix_sync(g_hp + (size_t)(base + m * 16) * HCC + wid * 16, c, HCC,
                                    wmma::mem_row_major);
        }
    }
}

// ---------------- a_src / a_dst from g_hp (R6-proven) ----------------
__global__ void k_attn(const float* __restrict__ atts, const float* __restrict__ attd) {
    __shared__ float ss[HCC], sd[HCC];
    int t = threadIdx.x;
    if (t < HCC) { ss[t] = atts[t]; sd[t] = attd[t]; }
    __syncthreads();
    int n = blockIdx.x * 8 + (t >> 5);
    if (n >= NN) return;
    int lane = t & 31;
    float4 p = ((const float4*)g_hp)[n * 32 + lane];
    int c = lane * 4;
    float vs = p.x * ss[c] + p.y * ss[c + 1] + p.z * ss[c + 2] + p.w * ss[c + 3];
    float vd = p.x * sd[c] + p.y * sd[c + 1] + p.z * sd[c + 2] + p.w * sd[c + 3];
    #pragma unroll
    for (int o = 4; o; o >>= 1) {
        vs += __shfl_xor_sync(~0u, vs, o);
        vd += __shfl_xor_sync(~0u, vd, o);
    }
    if ((lane & 7) == 0) {
        g_asrc[n * NHH + (lane >> 3)] = vs;
        g_adst[n * NHH + (lane >> 3)] = vd;
    }
}

// ---- single-pass softmax-aggregate (R6-proven serial form, + split-bf16 h store) ----
__global__ void k_agg(const float* __restrict__ bias, const float* __restrict__ gam,
                      const float* __restrict__ bet, int layer) {
    int t = threadIdx.x;
    int n = blockIdx.x * 8 + (t >> 5);
    if (n >= NN) return;
    int lane = t & 31;
    int hh = lane >> 3;
    int o0 = g_off[n];
    int deg = g_off[n + 1] - o0;
    float adh = g_adst[n * NHH + hh];
    const float* PAf = (const float*)d_PA + layer * 4 + hh;   // stride 16 per index
    const float* PBf = (const float*)d_PB + layer * 4 + hh;
    const float* SAf = (const float*)d_SA + layer * 4 + hh;
    const float* SBf = (const float*)d_SB + layer * 4 + hh;
    float cb = ((const float*)d_CB)[layer * 4 + hh];
    const float4* hp4 = (const float4*)g_hp;

    float4 acc = make_float4(0.f, 0.f, 0.f, 0.f);
    float den = 0.f;
    int j = 0;
    for (; j + 1 < deg; j += 2) {
        int p0 = o0 + j, p1 = o0 + j + 1;
        int s0 = g_csr_src[p0], s1 = g_csr_src[p1];
        float tv0 = g_tcsr[p0], tv1 = g_tcsr[p1];
        uchar2 ij0 = g_ij[p0], ij1 = g_ij[p1];
        float as0 = g_asrc[s0 * NHH + hh], as1 = g_asrc[s1 * NHH + hh];
        float4 hp0 = hp4[s0 * 32 + lane];
        float4 hp1 = hp4[s1 * 32 + lane];
        float ae0 = tv0 * (PAf[ij0.x * 16] + SAf[ij0.y * 16]) + PBf[ij0.x * 16] + SBf[ij0.y * 16] + cb;
        float ae1 = tv1 * (PAf[ij1.x * 16] + SAf[ij1.y * 16]) + PBf[ij1.x * 16] + SBf[ij1.y * 16] + cb;
        float a0 = as0 + adh + ae0; a0 = a0 >= 0.f ? a0 : 0.2f * a0;
        float a1 = as1 + adh + ae1; a1 = a1 >= 0.f ? a1 : 0.2f * a1;
        float w0 = __expf(a0);
        float w1 = __expf(a1);
        den += w0 + w1;
        acc.x += w0 * hp0.x + w1 * hp1.x;
        acc.y += w0 * hp0.y + w1 * hp1.y;
        acc.z += w0 * hp0.z + w1 * hp1.z;
        acc.w += w0 * hp0.w + w1 * hp1.w;
    }
    if (j < deg) {
        int p = o0 + j;
        int s = g_csr_src[p];
        float tv = g_tcsr[p];
        uchar2 ij = g_ij[p];
        float ae = tv * (PAf[ij.x * 16] + SAf[ij.y * 16]) + PBf[ij.x * 16] + SBf[ij.y * 16] + cb;
        float a = g_asrc[s * NHH + hh] + adh + ae;
        a = a >= 0.f ? a : 0.2f * a;
        float w = __expf(a);
        float4 hp = hp4[s * 32 + lane];
        den += w;
        acc.x += w * hp.x; acc.y += w * hp.y; acc.z += w * hp.z; acc.w += w * hp.w;
    }
    float rden = den > 0.f ? 1.f / den : 0.f;

    float4 bv = ((const float4*)bias)[lane];
    float4 v = make_float4(acc.x * rden + bv.x, acc.y * rden + bv.y,
                           acc.z * rden + bv.z, acc.w * rden + bv.w);
    float s1 = v.x + v.y + v.z + v.w;
    float s2 = v.x * v.x + v.y * v.y + v.z * v.z + v.w * v.w;
    #pragma unroll
    for (int o = 16; o; o >>= 1) {
        s1 += __shfl_xor_sync(~0u, s1, o);
        s2 += __shfl_xor_sync(~0u, s2, o);
    }
    float mean = s1 * (1.f / HCC);
    float var = s2 * (1.f / HCC) - mean * mean;
    float rstd = rsqrtf(var + 1e-5f);
    float4 gv = ((const float4*)gam)[lane];
    float4 bev = ((const float4*)bet)[lane];
    float4 hold = ((const float4*)g_h)[n * 32 + lane];
    float4 r;
    r.x = hold.x + fmaxf((v.x - mean) * rstd * gv.x + bev.x, 0.f);
    r.y = hold.y + fmaxf((v.y - mean) * rstd * gv.y + bev.y, 0.f);
    r.z = hold.z + fmaxf((v.z - mean) * rstd * gv.z + bev.z, 0.f);
    r.w = hold.w + fmaxf((v.w - mean) * rstd * gv.w + bev.w, 0.f);
    ((float4*)g_h)[n * 32 + lane] = r;
    if (layer < NLAY - 1) {          // split form needed only for the next layer's GEMM
        int o4 = n * HCC + lane * 4;
        split_store(r.x, &g_hbh[o4],     &g_hbl[o4]);
        split_store(r.y, &g_hbh[o4 + 1], &g_hbl[o4 + 1]);
        split_store(r.z, &g_hbh[o4 + 2], &g_hbl[o4 + 2]);
        split_store(r.w, &g_hbh[o4 + 3], &g_hbl[o4 + 3]);
    }
}

// ---------------- pooling (count folded in) + classifier ----------------
__global__ void k_pool(const int* __restrict__ batch) {
    int n0 = blockIdx.x * 256;
    int n1 = n0 + 256; if (n1 > NN) n1 = NN;
    int c = threadIdx.x;
    float run = 0.f, runc = 0.f;
    int curb = batch[n0];
    for (int n = n0; n < n1; n++) {
        int b = batch[n];
        if (b != curb) {
            atomicAdd(&g_sums[curb * HCC + c], run);
            if (c == 0) atomicAdd(&g_cnt[curb], runc);
            run = 0.f; runc = 0.f; curb = b;
        }
        run += g_h[n * HCC + c];
        runc += 1.f;
    }
    atomicAdd(&g_sums[curb * HCC + c], run);
    if (c == 0) atomicAdd(&g_cnt[curb], runc);
}
__global__ void k_cls(const float* __restrict__ W1, const float* __restrict__ b1,
                      const float* __restrict__ W2, const float* __restrict__ b2,
                      float* __restrict__ out) {
    __shared__ float sp[HCC];
    __shared__ float sz[64];
    int b = blockIdx.x;
    int c = threadIdx.x;
    float cnt = fmaxf(g_cnt[b], 1.f);
    sp[c] = g_sums[b * HCC + c] / cnt;
    __syncthreads();
    if (c < 64) {
        float a = b1[c];
        #pragma unroll 4
        for (int k = 0; k < HCC; k++) a += sp[k] * W1[k * 64 + c];
        sz[c] = fmaxf(a, 0.f);
    }
    __syncthreads();
    if (c < NCLS) {
        float a = b2[c];
        #pragma unroll 4
        for (int k = 0; k < 64; k++) a += sz[k] * W2[k * NCLS + c];
        out[b * NCLS + c] = a;
    }
}

// ---------------- launch ----------------
extern "C" void kernel_launch(void* const* d_in, const int* in_sizes, int n_in,
                              void* d_out, int out_size) {
    (void)in_sizes; (void)n_in; (void)out_size;
    const float* x     = (const float*)d_in[0];
    const float* eattr = (const float*)d_in[1];
    const int*   eidx  = (const int*)d_in[2];
    const int*   batch = (const int*)d_in[3];
    const float* W_ne  = (const float*)d_in[4];
    const float* b_ne  = (const float*)d_in[5];
    const float* g_ne  = (const float*)d_in[6];
    const float* be_ne = (const float*)d_in[7];
    const float* W_ee  = (const float*)d_in[8];
    const float* b_ee  = (const float*)d_in[9];
    const float* Wl    = (const float*)d_in[10];
    const float* att_s = (const float*)d_in[11];
    const float* att_d = (const float*)d_in[12];
    const float* We    = (const float*)d_in[13];
    const float* att_e = (const float*)d_in[14];
    const float* b_l   = (const float*)d_in[15];
    const float* g_l   = (const float*)d_in[16];
    const float* be_l  = (const float*)d_in[17];
    const float* W1    = (const float*)d_in[18];
    const float* b1    = (const float*)d_in[19];
    const float* W2    = (const float*)d_in[20];
    const float* b2    = (const float*)d_in[21];
    float* out = (float*)d_out;

    const int* src = eidx;
    const int* dst = eidx + EE;

    // tables first (k_scatter needs thresholds)
    k_prep<<<1, HCC>>>(We, att_e, W_ee, b_ee);
    k_wconv<<<(NLAY * HCC * HCC + 255) / 256, 256>>>(Wl);

    // CSR build + zero
    k_zero<<<(NN + 255) / 256, 256>>>();
    k_hist<<<(EE + 255) / 256, 256>>>(dst);
    k_scan1<<<49, 1024>>>();
    k_scan2<<<1, 64>>>();
    k_scan3<<<(NN + 255) / 256, 256>>>();
    k_scatter<<<(EE + 255) / 256, 256>>>(src, dst, eattr);

    // node encoder
    k_node_enc<<<(NN + 7) / 8, 256>>>(x, W_ne, b_ne, g_ne, be_ne);

    for (int l = 0; l < NLAY; l++) {
        k_gemm<<<296, 256>>>(l);
        k_attn<<<(NN + 7) / 8, 256>>>(att_s + l * HCC, att_d + l * HCC);
        k_agg<<<(NN + 7) / 8, 256>>>(b_l + l * HCC, g_l + l * HCC, be_l + l * HCC, l);
    }

    // pooling + classifier
    k_pool<<<(NN + 255) / 256, HCC>>>(batch);
    k_cls<<<NBATCH, HCC>>>(W1, b1, W2, b2, out);
}